// round 5
// baseline (speedup 1.0000x reference)
#include <cuda_runtime.h>

#define NN 100000
#define EE 1600000
#define ET 1700000   // EE + NN self loops
#define FIN 128
#define HD 64
#define CC 10

#define SCAN_T 1024
#define SCAN_E 4
#define SCAN_CHUNK (SCAN_T * SCAN_E)                 // 4096
#define SCAN_B ((NN + SCAN_CHUNK - 1) / SCAN_CHUNK)  // 25

// ---- static device scratch (no dynamic allocation allowed) ----
__device__ float4 g_h[2][NN * (HD / 4)];   // two ping-pong feature buffers
__device__ float  g_inv[2][NN];            // per-node 1/||h|| for each buffer
__device__ int    g_deg[NN];
__device__ int    g_rowptr[NN + 1];
__device__ int    g_cursor[NN];
__device__ int    g_csrc[ET];
__device__ int    g_is64;                  // edge_index dtype flag
__device__ int    g_bsum[SCAN_B];
__device__ int    g_boff[SCAN_B];

// packed fp32x2 FMA (2x scalar FFMA throughput; exact fp32 numerics)
__device__ __forceinline__ void ffma2(float2& d, float a, float2 b) {
    float2 av = make_float2(a, a);
    unsigned long long aa = *(unsigned long long*)&av;
    unsigned long long bb = *(unsigned long long*)&b;
    unsigned long long dd = *(unsigned long long*)&d;
    asm("fma.rn.f32x2 %0, %1, %2, %0;" : "+l"(dd) : "l"(aa), "l"(bb));
    d = *(float2*)&dd;
}

// ---------------------------------------------------------------
// dtype detection: int64 edge data (values < 2^31) has zero high words
// ---------------------------------------------------------------
__global__ void detect_kernel(const int* __restrict__ p) {
    if (threadIdx.x == 0 && blockIdx.x == 0) {
        int ornz = 0;
#pragma unroll
        for (int i = 0; i < 16; i++) ornz |= p[2 * i + 1];
        g_is64 = (ornz == 0) ? 1 : 0;
    }
}

__device__ __forceinline__ int edge_at(const void* ei, long long idx, int is64) {
    int v = is64 ? (int)((const long long*)ei)[idx] : ((const int*)ei)[idx];
    v = v < 0 ? 0 : (v >= NN ? NN - 1 : v);   // defensive clamp (no-op normally)
    return v;
}

// ---------------------------------------------------------------
// CSR build
// ---------------------------------------------------------------
__global__ void init_deg_kernel() {
    int i = blockIdx.x * blockDim.x + threadIdx.x;
    if (i < NN) g_deg[i] = 1;   // self loop pre-counted
}

__global__ void build_deg_kernel(const void* __restrict__ ei) {
    int i = blockIdx.x * blockDim.x + threadIdx.x;
    if (i < EE) {
        int is64 = g_is64;
        int d = edge_at(ei, (long long)EE + i, is64);
        atomicAdd(&g_deg[d], 1);
    }
}

// ---- 3-phase parallel exclusive scan of g_deg -> g_rowptr/g_cursor ----
__global__ void scan_bsum_kernel() {
    __shared__ int sh[SCAN_T];
    int t = threadIdx.x;
    int base = blockIdx.x * SCAN_CHUNK + t * SCAN_E;
    int s = 0;
#pragma unroll
    for (int k = 0; k < SCAN_E; k++) {
        int i = base + k;
        if (i < NN) s += g_deg[i];
    }
    sh[t] = s;
    __syncthreads();
    for (int off = SCAN_T / 2; off > 0; off >>= 1) {
        if (t < off) sh[t] += sh[t + off];
        __syncthreads();
    }
    if (t == 0) g_bsum[blockIdx.x] = sh[0];
}

__global__ void scan_boff_kernel() {
    int t = threadIdx.x;
    int v = (t < SCAN_B) ? g_bsum[t] : 0;
#pragma unroll
    for (int off = 1; off < 32; off <<= 1) {
        int u = __shfl_up_sync(0xFFFFFFFFu, v, off);
        if (t >= off) v += u;
    }
    if (t < SCAN_B) {
        int own = g_bsum[t];
        g_boff[t] = v - own;
    }
}

__global__ void scan_write_kernel() {
    __shared__ int sh[SCAN_T];
    int t = threadIdx.x;
    int base = blockIdx.x * SCAN_CHUNK + t * SCAN_E;
    int d[SCAN_E];
    int s = 0;
#pragma unroll
    for (int k = 0; k < SCAN_E; k++) {
        int i = base + k;
        d[k] = (i < NN) ? g_deg[i] : 0;
        s += d[k];
    }
    sh[t] = s;
    __syncthreads();
    for (int off = 1; off < SCAN_T; off <<= 1) {
        int v = (t >= off) ? sh[t - off] : 0;
        __syncthreads();
        sh[t] += v;
        __syncthreads();
    }
    int run = g_boff[blockIdx.x] + ((t == 0) ? 0 : sh[t - 1]);
#pragma unroll
    for (int k = 0; k < SCAN_E; k++) {
        int i = base + k;
        if (i < NN) {
            g_rowptr[i] = run;
            g_cursor[i] = run;
            run += d[k];
        }
    }
    if (blockIdx.x == 0 && t == 0) g_rowptr[NN] = ET;
}

__global__ void scatter_kernel(const void* __restrict__ ei) {
    int i = blockIdx.x * blockDim.x + threadIdx.x;
    if (i >= ET) return;
    int s, d;
    if (i < EE) {
        int is64 = g_is64;
        s = edge_at(ei, i, is64);
        d = edge_at(ei, (long long)EE + i, is64);
    } else {
        s = d = i - EE;
    }
    int pos = atomicAdd(&g_cursor[d], 1);
    if (pos >= 0 && pos < ET) g_csrc[pos] = s;
}

// ---------------------------------------------------------------
// GEMM1: h0 = relu(x @ W1 + b1), fused row-norm.
// 16 nodes/block; thread = (node, 4 columns); packed f32x2 FMA.
// ---------------------------------------------------------------
#define G1_NODES 16
__global__ void gemm1_kernel(const float* __restrict__ x,
                             const float* __restrict__ W1,
                             const float* __restrict__ b1) {
    __shared__ float ws[FIN * HD];          // 32 KB
    __shared__ float xs[G1_NODES * FIN];    // 8 KB
    int tid = threadIdx.x;
    for (int i = tid; i < FIN * HD; i += 256) ws[i] = W1[i];
    {
        const float4* xv = (const float4*)(x + (size_t)blockIdx.x * G1_NODES * FIN);
        float4* xsv = (float4*)xs;
#pragma unroll
        for (int i = tid; i < G1_NODES * FIN / 4; i += 256) xsv[i] = xv[i];
    }
    __syncthreads();

    int nl = tid >> 4;           // local node 0..15
    int cq = tid & 15;           // column quad 0..15
    int c  = cq * 4;
    int node = blockIdx.x * G1_NODES + nl;

    const float* xrow = &xs[nl * FIN];
    float2 a01 = make_float2(0.f, 0.f);
    float2 a23 = make_float2(0.f, 0.f);
#pragma unroll 8
    for (int k = 0; k < FIN; k++) {
        float xk = xrow[k];
        float4 w = *(const float4*)&ws[k * HD + c];
        ffma2(a01, xk, make_float2(w.x, w.y));
        ffma2(a23, xk, make_float2(w.z, w.w));
    }
    float4 o;
    o.x = fmaxf(a01.x + b1[c + 0], 0.f);
    o.y = fmaxf(a01.y + b1[c + 1], 0.f);
    o.z = fmaxf(a23.x + b1[c + 2], 0.f);
    o.w = fmaxf(a23.y + b1[c + 3], 0.f);

    g_h[0][(size_t)node * 16 + cq] = o;

    float sq = o.x * o.x + o.y * o.y + o.z * o.z + o.w * o.w;
    sq += __shfl_xor_sync(0xFFFFFFFFu, sq, 8);
    sq += __shfl_xor_sync(0xFFFFFFFFu, sq, 4);
    sq += __shfl_xor_sync(0xFFFFFFFFu, sq, 2);
    sq += __shfl_xor_sync(0xFFFFFFFFu, sq, 1);
    if (cq == 0) g_inv[0][node] = rsqrtf(fmaxf(sq, 1e-24f));
}

// ---------------------------------------------------------------
// Fused AGNN layer: warp per dst node, 4 edges in flight (8 lanes/edge).
// Adjacency chunk (32 edges) register-cached via one coalesced load;
// per-group src index obtained by shfl (no load-to-address dependency).
// No segment-max needed: alpha = cosine in [-1,1].
// ---------------------------------------------------------------
__global__ void agnn_kernel(int cur) {
    const float4* __restrict__ h   = g_h[cur];
    const float*  __restrict__ inv = g_inv[cur];
    float4* hout   = g_h[cur ^ 1];
    float*  invout = g_inv[cur ^ 1];

    int gw = (blockIdx.x * blockDim.x + threadIdx.x) >> 5;
    if (gw >= NN) return;
    int lane = threadIdx.x & 31;
    int grp  = lane >> 3;       // edge slot within iteration (0..3)
    int fl   = lane & 7;        // float4-pair index (0..7)

    float4 hd0 = h[(size_t)gw * 16 + 2 * fl];
    float4 hd1 = h[(size_t)gw * 16 + 2 * fl + 1];
    float  invd = inv[gw];
    int beg = g_rowptr[gw];
    int deg = g_rowptr[gw + 1] - beg;

    float4 acc0 = make_float4(0.f, 0.f, 0.f, 0.f);
    float4 acc1 = make_float4(0.f, 0.f, 0.f, 0.f);
    float denom = 0.f;

    for (int base = 0; base < deg; base += 32) {
        int rem = deg - base;
        int cnt = rem < 32 ? rem : 32;
        // one coalesced load covers the whole 32-edge chunk
        int s_all = (lane < cnt) ? g_csrc[beg + base + lane] : gw;
        int iters = (cnt + 3) >> 2;
#pragma unroll 4
        for (int it = 0; it < iters; it++) {
            int idx = 4 * it + grp;
            int s = __shfl_sync(0xFFFFFFFFu, s_all, idx);
            bool valid = idx < cnt;
            s = valid ? s : gw;
            float4 a = h[(size_t)s * 16 + 2 * fl];
            float4 b = h[(size_t)s * 16 + 2 * fl + 1];
            float invs = inv[s];
            float p = a.x * hd0.x + a.y * hd0.y + a.z * hd0.z + a.w * hd0.w
                    + b.x * hd1.x + b.y * hd1.y + b.z * hd1.z + b.w * hd1.w;
            p += __shfl_xor_sync(0xFFFFFFFFu, p, 4);
            p += __shfl_xor_sync(0xFFFFFFFFu, p, 2);
            p += __shfl_xor_sync(0xFFFFFFFFu, p, 1);
            float w = valid ? __expf(p * invd * invs) : 0.f;
            denom += w;
            acc0.x += w * a.x; acc0.y += w * a.y; acc0.z += w * a.z; acc0.w += w * a.w;
            acc1.x += w * b.x; acc1.y += w * b.y; acc1.z += w * b.z; acc1.w += w * b.w;
        }
    }

    // combine the 4 edge groups (lanes with same fl, different grp)
#pragma unroll
    for (int off = 8; off <= 16; off <<= 1) {
        acc0.x += __shfl_xor_sync(0xFFFFFFFFu, acc0.x, off);
        acc0.y += __shfl_xor_sync(0xFFFFFFFFu, acc0.y, off);
        acc0.z += __shfl_xor_sync(0xFFFFFFFFu, acc0.z, off);
        acc0.w += __shfl_xor_sync(0xFFFFFFFFu, acc0.w, off);
        acc1.x += __shfl_xor_sync(0xFFFFFFFFu, acc1.x, off);
        acc1.y += __shfl_xor_sync(0xFFFFFFFFu, acc1.y, off);
        acc1.z += __shfl_xor_sync(0xFFFFFFFFu, acc1.z, off);
        acc1.w += __shfl_xor_sync(0xFFFFFFFFu, acc1.w, off);
        denom  += __shfl_xor_sync(0xFFFFFFFFu, denom, off);
    }

    float r = 1.f / fmaxf(denom, 1e-16f);
    float4 o0 = make_float4(acc0.x * r, acc0.y * r, acc0.z * r, acc0.w * r);
    float4 o1 = make_float4(acc1.x * r, acc1.y * r, acc1.z * r, acc1.w * r);

    float sq = o0.x * o0.x + o0.y * o0.y + o0.z * o0.z + o0.w * o0.w
             + o1.x * o1.x + o1.y * o1.y + o1.z * o1.z + o1.w * o1.w;
    sq += __shfl_xor_sync(0xFFFFFFFFu, sq, 4);
    sq += __shfl_xor_sync(0xFFFFFFFFu, sq, 2);
    sq += __shfl_xor_sync(0xFFFFFFFFu, sq, 1);

    if (grp == 0) {
        hout[(size_t)gw * 16 + 2 * fl]     = o0;
        hout[(size_t)gw * 16 + 2 * fl + 1] = o1;
        if (fl == 0) invout[gw] = rsqrtf(fmaxf(sq, 1e-24f));
    }
}

// ---------------------------------------------------------------
// GEMM2 + log_softmax: thread per node
// ---------------------------------------------------------------
__global__ void gemm2_kernel(const float* __restrict__ W2,
                             const float* __restrict__ b2,
                             float* __restrict__ out, int cur) {
    __shared__ float w2s[HD * CC];
    __shared__ float b2s[CC];
    for (int i = threadIdx.x; i < HD * CC; i += blockDim.x) w2s[i] = W2[i];
    if (threadIdx.x < CC) b2s[threadIdx.x] = b2[threadIdx.x];
    __syncthreads();

    int node = blockIdx.x * blockDim.x + threadIdx.x;
    if (node >= NN) return;

    const float4* hp = (const float4*)g_h[cur] + (size_t)node * 16;
    float acc[CC];
#pragma unroll
    for (int j = 0; j < CC; j++) acc[j] = b2s[j];
#pragma unroll
    for (int k4 = 0; k4 < 16; k4++) {
        float4 hv = hp[k4];
#pragma unroll
        for (int j = 0; j < CC; j++) {
            acc[j] += hv.x * w2s[(4 * k4 + 0) * CC + j]
                    + hv.y * w2s[(4 * k4 + 1) * CC + j]
                    + hv.z * w2s[(4 * k4 + 2) * CC + j]
                    + hv.w * w2s[(4 * k4 + 3) * CC + j];
        }
    }
    float m = acc[0];
#pragma unroll
    for (int j = 1; j < CC; j++) m = fmaxf(m, acc[j]);
    float ssum = 0.f;
#pragma unroll
    for (int j = 0; j < CC; j++) ssum += __expf(acc[j] - m);
    float lse = m + logf(ssum);
#pragma unroll
    for (int j = 0; j < CC; j++) out[(size_t)node * CC + j] = acc[j] - lse;
}

// ---------------------------------------------------------------
extern "C" void kernel_launch(void* const* d_in, const int* in_sizes, int n_in,
                              void* d_out, int out_size) {
    const float* x = nullptr; const void* ei = nullptr;
    const float* W1 = nullptr; const float* b1 = nullptr;
    const float* W2 = nullptr; const float* b2 = nullptr;
    for (int i = 0; i < n_in; i++) {
        switch (in_sizes[i]) {
            case NN * FIN:   x  = (const float*)d_in[i]; break;
            case 2 * EE:     ei = d_in[i]; break;
            case FIN * HD:   W1 = (const float*)d_in[i]; break;
            case HD:         b1 = (const float*)d_in[i]; break;
            case HD * CC:    W2 = (const float*)d_in[i]; break;
            case CC:         b2 = (const float*)d_in[i]; break;
            default: break;
        }
    }
    float* out = (float*)d_out;

    detect_kernel<<<1, 32>>>((const int*)ei);
    init_deg_kernel<<<(NN + 255) / 256, 256>>>();
    build_deg_kernel<<<(EE + 255) / 256, 256>>>(ei);
    scan_bsum_kernel<<<SCAN_B, SCAN_T>>>();
    scan_boff_kernel<<<1, 32>>>();
    scan_write_kernel<<<SCAN_B, SCAN_T>>>();
    scatter_kernel<<<(ET + 255) / 256, 256>>>(ei);

    gemm1_kernel<<<NN / G1_NODES, 256>>>(x, W1, b1);

    for (int l = 0; l < 4; l++)
        agnn_kernel<<<(NN + 7) / 8, 256>>>(l & 1);

    gemm2_kernel<<<(NN + 255) / 256, 256>>>(W2, b2, out, 0);
}

// round 6
// speedup vs baseline: 1.0469x; 1.0469x over previous
#include <cuda_runtime.h>

#define NN 100000
#define EE 1600000
#define ET 1700000   // EE + NN self loops
#define FIN 128
#define HD 64
#define CC 10

#define SCAN_T 1024
#define SCAN_E 4
#define SCAN_CHUNK (SCAN_T * SCAN_E)                 // 4096
#define SCAN_B ((NN + SCAN_CHUNK - 1) / SCAN_CHUNK)  // 25

// ---- static device scratch (no dynamic allocation allowed) ----
__device__ float4 g_h[2][NN * (HD / 4)];   // two ping-pong feature buffers
__device__ float  g_inv[2][NN];            // per-node 1/||h|| for each buffer
__device__ int    g_deg[NN];
__device__ int    g_rowptr[NN + 1];
__device__ int    g_cursor[NN];
__device__ int    g_csrc[ET];
__device__ int    g_is64;                  // edge_index dtype flag
__device__ int    g_bsum[SCAN_B];
__device__ int    g_boff[SCAN_B];

// packed fp32x2 FMA (2x scalar FFMA throughput; exact fp32 numerics)
__device__ __forceinline__ void ffma2(float2& d, float a, float2 b) {
    float2 av = make_float2(a, a);
    unsigned long long aa = *(unsigned long long*)&av;
    unsigned long long bb = *(unsigned long long*)&b;
    unsigned long long dd = *(unsigned long long*)&d;
    asm("fma.rn.f32x2 %0, %1, %2, %0;" : "+l"(dd) : "l"(aa), "l"(bb));
    d = *(float2*)&dd;
}

// ---------------------------------------------------------------
// dtype detection: int64 edge data (values < 2^31) has zero high words
// ---------------------------------------------------------------
__global__ void detect_kernel(const int* __restrict__ p) {
    if (threadIdx.x == 0 && blockIdx.x == 0) {
        int ornz = 0;
#pragma unroll
        for (int i = 0; i < 16; i++) ornz |= p[2 * i + 1];
        g_is64 = (ornz == 0) ? 1 : 0;
    }
}

__device__ __forceinline__ int edge_at(const void* ei, long long idx, int is64) {
    int v = is64 ? (int)((const long long*)ei)[idx] : ((const int*)ei)[idx];
    v = v < 0 ? 0 : (v >= NN ? NN - 1 : v);   // defensive clamp (no-op normally)
    return v;
}

// ---------------------------------------------------------------
// CSR build
// ---------------------------------------------------------------
__global__ void init_deg_kernel() {
    int i = blockIdx.x * blockDim.x + threadIdx.x;
    if (i < NN) g_deg[i] = 1;   // self loop pre-counted
}

__global__ void build_deg_kernel(const void* __restrict__ ei) {
    int i = blockIdx.x * blockDim.x + threadIdx.x;
    if (i < EE) {
        int is64 = g_is64;
        int d = edge_at(ei, (long long)EE + i, is64);
        atomicAdd(&g_deg[d], 1);
    }
}

// ---- 3-phase parallel exclusive scan of g_deg -> g_rowptr/g_cursor ----
__global__ void scan_bsum_kernel() {
    __shared__ int sh[SCAN_T];
    int t = threadIdx.x;
    int base = blockIdx.x * SCAN_CHUNK + t * SCAN_E;
    int s = 0;
#pragma unroll
    for (int k = 0; k < SCAN_E; k++) {
        int i = base + k;
        if (i < NN) s += g_deg[i];
    }
    sh[t] = s;
    __syncthreads();
    for (int off = SCAN_T / 2; off > 0; off >>= 1) {
        if (t < off) sh[t] += sh[t + off];
        __syncthreads();
    }
    if (t == 0) g_bsum[blockIdx.x] = sh[0];
}

__global__ void scan_boff_kernel() {
    int t = threadIdx.x;
    int v = (t < SCAN_B) ? g_bsum[t] : 0;
#pragma unroll
    for (int off = 1; off < 32; off <<= 1) {
        int u = __shfl_up_sync(0xFFFFFFFFu, v, off);
        if (t >= off) v += u;
    }
    if (t < SCAN_B) {
        int own = g_bsum[t];
        g_boff[t] = v - own;
    }
}

__global__ void scan_write_kernel() {
    __shared__ int sh[SCAN_T];
    int t = threadIdx.x;
    int base = blockIdx.x * SCAN_CHUNK + t * SCAN_E;
    int d[SCAN_E];
    int s = 0;
#pragma unroll
    for (int k = 0; k < SCAN_E; k++) {
        int i = base + k;
        d[k] = (i < NN) ? g_deg[i] : 0;
        s += d[k];
    }
    sh[t] = s;
    __syncthreads();
    for (int off = 1; off < SCAN_T; off <<= 1) {
        int v = (t >= off) ? sh[t - off] : 0;
        __syncthreads();
        sh[t] += v;
        __syncthreads();
    }
    int run = g_boff[blockIdx.x] + ((t == 0) ? 0 : sh[t - 1]);
#pragma unroll
    for (int k = 0; k < SCAN_E; k++) {
        int i = base + k;
        if (i < NN) {
            g_rowptr[i] = run;
            g_cursor[i] = run;
            run += d[k];
        }
    }
    if (blockIdx.x == 0 && t == 0) g_rowptr[NN] = ET;
}

__global__ void scatter_kernel(const void* __restrict__ ei) {
    int i = blockIdx.x * blockDim.x + threadIdx.x;
    if (i >= ET) return;
    int s, d;
    if (i < EE) {
        int is64 = g_is64;
        s = edge_at(ei, i, is64);
        d = edge_at(ei, (long long)EE + i, is64);
    } else {
        s = d = i - EE;
    }
    int pos = atomicAdd(&g_cursor[d], 1);
    if (pos >= 0 && pos < ET) g_csrc[pos] = s;
}

// ---------------------------------------------------------------
// GEMM1: h0 = relu(x @ W1 + b1), fused row-norm.
// 16 nodes/block; thread = (node, 4 columns); packed f32x2 FMA.
// ---------------------------------------------------------------
#define G1_NODES 16
__global__ void gemm1_kernel(const float* __restrict__ x,
                             const float* __restrict__ W1,
                             const float* __restrict__ b1) {
    __shared__ float ws[FIN * HD];          // 32 KB
    __shared__ float xs[G1_NODES * FIN];    // 8 KB
    int tid = threadIdx.x;
    for (int i = tid; i < FIN * HD; i += 256) ws[i] = W1[i];
    {
        const float4* xv = (const float4*)(x + (size_t)blockIdx.x * G1_NODES * FIN);
        float4* xsv = (float4*)xs;
#pragma unroll
        for (int i = tid; i < G1_NODES * FIN / 4; i += 256) xsv[i] = xv[i];
    }
    __syncthreads();

    int nl = tid >> 4;           // local node 0..15
    int cq = tid & 15;           // column quad 0..15
    int c  = cq * 4;
    int node = blockIdx.x * G1_NODES + nl;

    const float* xrow = &xs[nl * FIN];
    float2 a01 = make_float2(0.f, 0.f);
    float2 a23 = make_float2(0.f, 0.f);
#pragma unroll 8
    for (int k = 0; k < FIN; k++) {
        float xk = xrow[k];
        float4 w = *(const float4*)&ws[k * HD + c];
        ffma2(a01, xk, make_float2(w.x, w.y));
        ffma2(a23, xk, make_float2(w.z, w.w));
    }
    float4 o;
    o.x = fmaxf(a01.x + b1[c + 0], 0.f);
    o.y = fmaxf(a01.y + b1[c + 1], 0.f);
    o.z = fmaxf(a23.x + b1[c + 2], 0.f);
    o.w = fmaxf(a23.y + b1[c + 3], 0.f);

    g_h[0][(size_t)node * 16 + cq] = o;

    float sq = o.x * o.x + o.y * o.y + o.z * o.z + o.w * o.w;
    sq += __shfl_xor_sync(0xFFFFFFFFu, sq, 8);
    sq += __shfl_xor_sync(0xFFFFFFFFu, sq, 4);
    sq += __shfl_xor_sync(0xFFFFFFFFu, sq, 2);
    sq += __shfl_xor_sync(0xFFFFFFFFu, sq, 1);
    if (cq == 0) g_inv[0][node] = rsqrtf(fmaxf(sq, 1e-24f));
}

// ---------------------------------------------------------------
// Fused AGNN layer: warp per dst node, 4 edges in flight (8 lanes/edge).
// Edge index for iteration it+1 is prefetched at the top of iteration it,
// so the h-row gather addresses are always ready (no load-to-address stall).
// No segment-max needed: alpha = cosine in [-1,1].
// ---------------------------------------------------------------
__global__ void agnn_kernel(int cur) {
    const float4* __restrict__ h   = g_h[cur];
    const float*  __restrict__ inv = g_inv[cur];
    float4* hout   = g_h[cur ^ 1];
    float*  invout = g_inv[cur ^ 1];

    int gw = (blockIdx.x * blockDim.x + threadIdx.x) >> 5;
    if (gw >= NN) return;
    int lane = threadIdx.x & 31;
    int grp  = lane >> 3;       // edge slot within iteration (0..3)
    int fl   = lane & 7;        // float4-pair index (0..7)

    float4 hd0 = h[(size_t)gw * 16 + 2 * fl];
    float4 hd1 = h[(size_t)gw * 16 + 2 * fl + 1];
    float  invd = inv[gw];
    int beg = g_rowptr[gw];
    int end = g_rowptr[gw + 1];

    float4 acc0 = make_float4(0.f, 0.f, 0.f, 0.f);
    float4 acc1 = make_float4(0.f, 0.f, 0.f, 0.f);
    float denom = 0.f;

    int iters = (end - beg + 3) >> 2;
    int e0 = beg + grp;
    bool v_next = e0 < end;
    int s_next = v_next ? g_csrc[e0] : gw;

#pragma unroll 2
    for (int it = 0; it < iters; it++) {
        int s = s_next;
        bool valid = v_next;
        // prefetch next iteration's edge index (hides csrc latency)
        int en = beg + 4 * (it + 1) + grp;
        v_next = en < end;
        s_next = v_next ? g_csrc[en] : gw;

        float4 a = h[(size_t)s * 16 + 2 * fl];
        float4 b = h[(size_t)s * 16 + 2 * fl + 1];
        float invs = inv[s];
        float p = a.x * hd0.x + a.y * hd0.y + a.z * hd0.z + a.w * hd0.w
                + b.x * hd1.x + b.y * hd1.y + b.z * hd1.z + b.w * hd1.w;
        p += __shfl_xor_sync(0xFFFFFFFFu, p, 4);
        p += __shfl_xor_sync(0xFFFFFFFFu, p, 2);
        p += __shfl_xor_sync(0xFFFFFFFFu, p, 1);
        float w = valid ? __expf(p * invd * invs) : 0.f;
        denom += w;
        acc0.x += w * a.x; acc0.y += w * a.y; acc0.z += w * a.z; acc0.w += w * a.w;
        acc1.x += w * b.x; acc1.y += w * b.y; acc1.z += w * b.z; acc1.w += w * b.w;
    }

    // combine the 4 edge groups (lanes with same fl, different grp)
#pragma unroll
    for (int off = 8; off <= 16; off <<= 1) {
        acc0.x += __shfl_xor_sync(0xFFFFFFFFu, acc0.x, off);
        acc0.y += __shfl_xor_sync(0xFFFFFFFFu, acc0.y, off);
        acc0.z += __shfl_xor_sync(0xFFFFFFFFu, acc0.z, off);
        acc0.w += __shfl_xor_sync(0xFFFFFFFFu, acc0.w, off);
        acc1.x += __shfl_xor_sync(0xFFFFFFFFu, acc1.x, off);
        acc1.y += __shfl_xor_sync(0xFFFFFFFFu, acc1.y, off);
        acc1.z += __shfl_xor_sync(0xFFFFFFFFu, acc1.z, off);
        acc1.w += __shfl_xor_sync(0xFFFFFFFFu, acc1.w, off);
        denom  += __shfl_xor_sync(0xFFFFFFFFu, denom, off);
    }

    float r = 1.f / fmaxf(denom, 1e-16f);
    float4 o0 = make_float4(acc0.x * r, acc0.y * r, acc0.z * r, acc0.w * r);
    float4 o1 = make_float4(acc1.x * r, acc1.y * r, acc1.z * r, acc1.w * r);

    float sq = o0.x * o0.x + o0.y * o0.y + o0.z * o0.z + o0.w * o0.w
             + o1.x * o1.x + o1.y * o1.y + o1.z * o1.z + o1.w * o1.w;
    sq += __shfl_xor_sync(0xFFFFFFFFu, sq, 4);
    sq += __shfl_xor_sync(0xFFFFFFFFu, sq, 2);
    sq += __shfl_xor_sync(0xFFFFFFFFu, sq, 1);

    if (grp == 0) {
        hout[(size_t)gw * 16 + 2 * fl]     = o0;
        hout[(size_t)gw * 16 + 2 * fl + 1] = o1;
        if (fl == 0) invout[gw] = rsqrtf(fmaxf(sq, 1e-24f));
    }
}

// ---------------------------------------------------------------
// GEMM2 + log_softmax: thread per node
// ---------------------------------------------------------------
__global__ void gemm2_kernel(const float* __restrict__ W2,
                             const float* __restrict__ b2,
                             float* __restrict__ out, int cur) {
    __shared__ float w2s[HD * CC];
    __shared__ float b2s[CC];
    for (int i = threadIdx.x; i < HD * CC; i += blockDim.x) w2s[i] = W2[i];
    if (threadIdx.x < CC) b2s[threadIdx.x] = b2[threadIdx.x];
    __syncthreads();

    int node = blockIdx.x * blockDim.x + threadIdx.x;
    if (node >= NN) return;

    const float4* hp = (const float4*)g_h[cur] + (size_t)node * 16;
    float acc[CC];
#pragma unroll
    for (int j = 0; j < CC; j++) acc[j] = b2s[j];
#pragma unroll
    for (int k4 = 0; k4 < 16; k4++) {
        float4 hv = hp[k4];
#pragma unroll
        for (int j = 0; j < CC; j++) {
            acc[j] += hv.x * w2s[(4 * k4 + 0) * CC + j]
                    + hv.y * w2s[(4 * k4 + 1) * CC + j]
                    + hv.z * w2s[(4 * k4 + 2) * CC + j]
                    + hv.w * w2s[(4 * k4 + 3) * CC + j];
        }
    }
    float m = acc[0];
#pragma unroll
    for (int j = 1; j < CC; j++) m = fmaxf(m, acc[j]);
    float ssum = 0.f;
#pragma unroll
    for (int j = 0; j < CC; j++) ssum += __expf(acc[j] - m);
    float lse = m + logf(ssum);
#pragma unroll
    for (int j = 0; j < CC; j++) out[(size_t)node * CC + j] = acc[j] - lse;
}

// ---------------------------------------------------------------
extern "C" void kernel_launch(void* const* d_in, const int* in_sizes, int n_in,
                              void* d_out, int out_size) {
    const float* x = nullptr; const void* ei = nullptr;
    const float* W1 = nullptr; const float* b1 = nullptr;
    const float* W2 = nullptr; const float* b2 = nullptr;
    for (int i = 0; i < n_in; i++) {
        switch (in_sizes[i]) {
            case NN * FIN:   x  = (const float*)d_in[i]; break;
            case 2 * EE:     ei = d_in[i]; break;
            case FIN * HD:   W1 = (const float*)d_in[i]; break;
            case HD:         b1 = (const float*)d_in[i]; break;
            case HD * CC:    W2 = (const float*)d_in[i]; break;
            case CC:         b2 = (const float*)d_in[i]; break;
            default: break;
        }
    }
    float* out = (float*)d_out;

    detect_kernel<<<1, 32>>>((const int*)ei);
    init_deg_kernel<<<(NN + 255) / 256, 256>>>();
    build_deg_kernel<<<(EE + 255) / 256, 256>>>(ei);
    scan_bsum_kernel<<<SCAN_B, SCAN_T>>>();
    scan_boff_kernel<<<1, 32>>>();
    scan_write_kernel<<<SCAN_B, SCAN_T>>>();
    scatter_kernel<<<(ET + 255) / 256, 256>>>(ei);

    gemm1_kernel<<<NN / G1_NODES, 256>>>(x, W1, b1);

    for (int l = 0; l < 4; l++)
        agnn_kernel<<<(NN + 7) / 8, 256>>>(l & 1);

    gemm2_kernel<<<(NN + 255) / 256, 256>>>(W2, b2, out, 0);
}

// round 7
// speedup vs baseline: 1.0981x; 1.0489x over previous
#include <cuda_runtime.h>

#define NN 100000
#define EE 1600000
#define ET 1700000   // EE + NN self loops
#define FIN 128
#define HD 64
#define CC 10

#define SCAN_T 1024
#define SCAN_E 4
#define SCAN_CHUNK (SCAN_T * SCAN_E)                 // 4096
#define SCAN_B ((NN + SCAN_CHUNK - 1) / SCAN_CHUNK)  // 25

// ---- static device scratch (no dynamic allocation allowed) ----
__device__ float4 g_h[2][NN * (HD / 4)];   // two ping-pong feature buffers
__device__ float  g_inv[2][NN];            // per-node 1/||h|| for each buffer
__device__ int    g_deg[NN];
__device__ int    g_rowptr[NN + 1];
__device__ int    g_cursor[NN];
__device__ int    g_csrc[ET];
__device__ int    g_is64;                  // edge_index dtype flag
__device__ int    g_bsum[SCAN_B];
__device__ int    g_boff[SCAN_B];

// packed fp32x2 FMA (2x scalar FFMA throughput; exact fp32 numerics)
__device__ __forceinline__ void ffma2(float2& d, float a, float2 b) {
    float2 av = make_float2(a, a);
    unsigned long long aa = *(unsigned long long*)&av;
    unsigned long long bb = *(unsigned long long*)&b;
    unsigned long long dd = *(unsigned long long*)&d;
    asm("fma.rn.f32x2 %0, %1, %2, %0;" : "+l"(dd) : "l"(aa), "l"(bb));
    d = *(float2*)&dd;
}

// ---------------------------------------------------------------
// dtype detection: int64 edge data (values < 2^31) has zero high words
// ---------------------------------------------------------------
__global__ void detect_kernel(const int* __restrict__ p) {
    if (threadIdx.x == 0 && blockIdx.x == 0) {
        int ornz = 0;
#pragma unroll
        for (int i = 0; i < 16; i++) ornz |= p[2 * i + 1];
        g_is64 = (ornz == 0) ? 1 : 0;
    }
}

__device__ __forceinline__ int edge_at(const void* ei, long long idx, int is64) {
    int v = is64 ? (int)((const long long*)ei)[idx] : ((const int*)ei)[idx];
    v = v < 0 ? 0 : (v >= NN ? NN - 1 : v);   // defensive clamp (no-op normally)
    return v;
}

// ---------------------------------------------------------------
// CSR build
// ---------------------------------------------------------------
__global__ void init_deg_kernel() {
    int i = blockIdx.x * blockDim.x + threadIdx.x;
    if (i < NN) g_deg[i] = 1;   // self loop pre-counted
}

__global__ void build_deg_kernel(const void* __restrict__ ei) {
    int i = blockIdx.x * blockDim.x + threadIdx.x;
    if (i < EE) {
        int is64 = g_is64;
        int d = edge_at(ei, (long long)EE + i, is64);
        atomicAdd(&g_deg[d], 1);
    }
}

// ---- 3-phase parallel exclusive scan of g_deg -> g_rowptr/g_cursor ----
__global__ void scan_bsum_kernel() {
    __shared__ int sh[SCAN_T];
    int t = threadIdx.x;
    int base = blockIdx.x * SCAN_CHUNK + t * SCAN_E;
    int s = 0;
#pragma unroll
    for (int k = 0; k < SCAN_E; k++) {
        int i = base + k;
        if (i < NN) s += g_deg[i];
    }
    sh[t] = s;
    __syncthreads();
    for (int off = SCAN_T / 2; off > 0; off >>= 1) {
        if (t < off) sh[t] += sh[t + off];
        __syncthreads();
    }
    if (t == 0) g_bsum[blockIdx.x] = sh[0];
}

__global__ void scan_boff_kernel() {
    int t = threadIdx.x;
    int v = (t < SCAN_B) ? g_bsum[t] : 0;
#pragma unroll
    for (int off = 1; off < 32; off <<= 1) {
        int u = __shfl_up_sync(0xFFFFFFFFu, v, off);
        if (t >= off) v += u;
    }
    if (t < SCAN_B) {
        int own = g_bsum[t];
        g_boff[t] = v - own;
    }
}

__global__ void scan_write_kernel() {
    __shared__ int sh[SCAN_T];
    int t = threadIdx.x;
    int base = blockIdx.x * SCAN_CHUNK + t * SCAN_E;
    int d[SCAN_E];
    int s = 0;
#pragma unroll
    for (int k = 0; k < SCAN_E; k++) {
        int i = base + k;
        d[k] = (i < NN) ? g_deg[i] : 0;
        s += d[k];
    }
    sh[t] = s;
    __syncthreads();
    for (int off = 1; off < SCAN_T; off <<= 1) {
        int v = (t >= off) ? sh[t - off] : 0;
        __syncthreads();
        sh[t] += v;
        __syncthreads();
    }
    int run = g_boff[blockIdx.x] + ((t == 0) ? 0 : sh[t - 1]);
#pragma unroll
    for (int k = 0; k < SCAN_E; k++) {
        int i = base + k;
        if (i < NN) {
            g_rowptr[i] = run;
            g_cursor[i] = run;
            run += d[k];
        }
    }
    if (blockIdx.x == 0 && t == 0) g_rowptr[NN] = ET;
}

__global__ void scatter_kernel(const void* __restrict__ ei) {
    int i = blockIdx.x * blockDim.x + threadIdx.x;
    if (i >= ET) return;
    int s, d;
    if (i < EE) {
        int is64 = g_is64;
        s = edge_at(ei, i, is64);
        d = edge_at(ei, (long long)EE + i, is64);
    } else {
        s = d = i - EE;
    }
    int pos = atomicAdd(&g_cursor[d], 1);
    if (pos >= 0 && pos < ET) g_csrc[pos] = s;
}

// ---------------------------------------------------------------
// GEMM1: h0 = relu(x @ W1 + b1), fused row-norm.
// 16 nodes/block; thread = (node, 4 columns); packed f32x2 FMA.
// ---------------------------------------------------------------
#define G1_NODES 16
__global__ void gemm1_kernel(const float* __restrict__ x,
                             const float* __restrict__ W1,
                             const float* __restrict__ b1) {
    __shared__ float ws[FIN * HD];          // 32 KB
    __shared__ float xs[G1_NODES * FIN];    // 8 KB
    int tid = threadIdx.x;
    for (int i = tid; i < FIN * HD; i += 256) ws[i] = W1[i];
    {
        const float4* xv = (const float4*)(x + (size_t)blockIdx.x * G1_NODES * FIN);
        float4* xsv = (float4*)xs;
#pragma unroll
        for (int i = tid; i < G1_NODES * FIN / 4; i += 256) xsv[i] = xv[i];
    }
    __syncthreads();

    int nl = tid >> 4;           // local node 0..15
    int cq = tid & 15;           // column quad 0..15
    int c  = cq * 4;
    int node = blockIdx.x * G1_NODES + nl;

    const float* xrow = &xs[nl * FIN];
    float2 a01 = make_float2(0.f, 0.f);
    float2 a23 = make_float2(0.f, 0.f);
#pragma unroll 8
    for (int k = 0; k < FIN; k++) {
        float xk = xrow[k];
        float4 w = *(const float4*)&ws[k * HD + c];
        ffma2(a01, xk, make_float2(w.x, w.y));
        ffma2(a23, xk, make_float2(w.z, w.w));
    }
    float4 o;
    o.x = fmaxf(a01.x + b1[c + 0], 0.f);
    o.y = fmaxf(a01.y + b1[c + 1], 0.f);
    o.z = fmaxf(a23.x + b1[c + 2], 0.f);
    o.w = fmaxf(a23.y + b1[c + 3], 0.f);

    g_h[0][(size_t)node * 16 + cq] = o;

    float sq = o.x * o.x + o.y * o.y + o.z * o.z + o.w * o.w;
    sq += __shfl_xor_sync(0xFFFFFFFFu, sq, 8);
    sq += __shfl_xor_sync(0xFFFFFFFFu, sq, 4);
    sq += __shfl_xor_sync(0xFFFFFFFFu, sq, 2);
    sq += __shfl_xor_sync(0xFFFFFFFFu, sq, 1);
    if (cq == 0) g_inv[0][node] = rsqrtf(fmaxf(sq, 1e-24f));
}

// ---------------------------------------------------------------
// Fused AGNN layer: warp per dst node, 4 edges in flight (8 lanes/edge).
// CONTIGUOUS gather layout: lane fl owns row quads {fl, fl+8}, so each
// 8-lane group's LDG.128 covers one 128B cache line (1 line/edge instead
// of 2) — halves L1tex wavefront count of the dominant loads.
// Edge index for iteration it+1 prefetched at the top of iteration it.
// No segment-max needed: alpha = cosine in [-1,1].
// ---------------------------------------------------------------
__global__ void agnn_kernel(int cur) {
    const float4* __restrict__ h   = g_h[cur];
    const float*  __restrict__ inv = g_inv[cur];
    float4* hout   = g_h[cur ^ 1];
    float*  invout = g_inv[cur ^ 1];

    int gw = (blockIdx.x * blockDim.x + threadIdx.x) >> 5;
    if (gw >= NN) return;
    int lane = threadIdx.x & 31;
    int grp  = lane >> 3;       // edge slot within iteration (0..3)
    int fl   = lane & 7;        // float4 index: owns quads fl and fl+8

    float4 hd0 = h[(size_t)gw * 16 + fl];
    float4 hd1 = h[(size_t)gw * 16 + fl + 8];
    float  invd = inv[gw];
    int beg = g_rowptr[gw];
    int end = g_rowptr[gw + 1];

    float4 acc0 = make_float4(0.f, 0.f, 0.f, 0.f);
    float4 acc1 = make_float4(0.f, 0.f, 0.f, 0.f);
    float denom = 0.f;

    int iters = (end - beg + 3) >> 2;
    int e0 = beg + grp;
    bool v_next = e0 < end;
    int s_next = v_next ? g_csrc[e0] : gw;

#pragma unroll 2
    for (int it = 0; it < iters; it++) {
        int s = s_next;
        bool valid = v_next;
        // prefetch next iteration's edge index (hides csrc latency)
        int en = beg + 4 * (it + 1) + grp;
        v_next = en < end;
        s_next = v_next ? g_csrc[en] : gw;

        float4 a = h[(size_t)s * 16 + fl];       // line 0 of src row
        float4 b = h[(size_t)s * 16 + fl + 8];   // line 1 of src row
        float invs = inv[s];
        float p = a.x * hd0.x + a.y * hd0.y + a.z * hd0.z + a.w * hd0.w
                + b.x * hd1.x + b.y * hd1.y + b.z * hd1.z + b.w * hd1.w;
        p += __shfl_xor_sync(0xFFFFFFFFu, p, 4);
        p += __shfl_xor_sync(0xFFFFFFFFu, p, 2);
        p += __shfl_xor_sync(0xFFFFFFFFu, p, 1);
        float w = valid ? __expf(p * invd * invs) : 0.f;
        denom += w;
        acc0.x += w * a.x; acc0.y += w * a.y; acc0.z += w * a.z; acc0.w += w * a.w;
        acc1.x += w * b.x; acc1.y += w * b.y; acc1.z += w * b.z; acc1.w += w * b.w;
    }

    // combine the 4 edge groups (lanes with same fl, different grp)
#pragma unroll
    for (int off = 8; off <= 16; off <<= 1) {
        acc0.x += __shfl_xor_sync(0xFFFFFFFFu, acc0.x, off);
        acc0.y += __shfl_xor_sync(0xFFFFFFFFu, acc0.y, off);
        acc0.z += __shfl_xor_sync(0xFFFFFFFFu, acc0.z, off);
        acc0.w += __shfl_xor_sync(0xFFFFFFFFu, acc0.w, off);
        acc1.x += __shfl_xor_sync(0xFFFFFFFFu, acc1.x, off);
        acc1.y += __shfl_xor_sync(0xFFFFFFFFu, acc1.y, off);
        acc1.z += __shfl_xor_sync(0xFFFFFFFFu, acc1.z, off);
        acc1.w += __shfl_xor_sync(0xFFFFFFFFu, acc1.w, off);
        denom  += __shfl_xor_sync(0xFFFFFFFFu, denom, off);
    }

    float r = 1.f / fmaxf(denom, 1e-16f);
    float4 o0 = make_float4(acc0.x * r, acc0.y * r, acc0.z * r, acc0.w * r);
    float4 o1 = make_float4(acc1.x * r, acc1.y * r, acc1.z * r, acc1.w * r);

    float sq = o0.x * o0.x + o0.y * o0.y + o0.z * o0.z + o0.w * o0.w
             + o1.x * o1.x + o1.y * o1.y + o1.z * o1.z + o1.w * o1.w;
    sq += __shfl_xor_sync(0xFFFFFFFFu, sq, 4);
    sq += __shfl_xor_sync(0xFFFFFFFFu, sq, 2);
    sq += __shfl_xor_sync(0xFFFFFFFFu, sq, 1);

    if (grp == 0) {
        hout[(size_t)gw * 16 + fl]     = o0;
        hout[(size_t)gw * 16 + fl + 8] = o1;
        if (fl == 0) invout[gw] = rsqrtf(fmaxf(sq, 1e-24f));
    }
}

// ---------------------------------------------------------------
// GEMM2 + log_softmax: thread per node
// ---------------------------------------------------------------
__global__ void gemm2_kernel(const float* __restrict__ W2,
                             const float* __restrict__ b2,
                             float* __restrict__ out, int cur) {
    __shared__ float w2s[HD * CC];
    __shared__ float b2s[CC];
    for (int i = threadIdx.x; i < HD * CC; i += blockDim.x) w2s[i] = W2[i];
    if (threadIdx.x < CC) b2s[threadIdx.x] = b2[threadIdx.x];
    __syncthreads();

    int node = blockIdx.x * blockDim.x + threadIdx.x;
    if (node >= NN) return;

    const float4* hp = (const float4*)g_h[cur] + (size_t)node * 16;
    float acc[CC];
#pragma unroll
    for (int j = 0; j < CC; j++) acc[j] = b2s[j];
#pragma unroll
    for (int k4 = 0; k4 < 16; k4++) {
        float4 hv = hp[k4];
#pragma unroll
        for (int j = 0; j < CC; j++) {
            acc[j] += hv.x * w2s[(4 * k4 + 0) * CC + j]
                    + hv.y * w2s[(4 * k4 + 1) * CC + j]
                    + hv.z * w2s[(4 * k4 + 2) * CC + j]
                    + hv.w * w2s[(4 * k4 + 3) * CC + j];
        }
    }
    float m = acc[0];
#pragma unroll
    for (int j = 1; j < CC; j++) m = fmaxf(m, acc[j]);
    float ssum = 0.f;
#pragma unroll
    for (int j = 0; j < CC; j++) ssum += __expf(acc[j] - m);
    float lse = m + logf(ssum);
#pragma unroll
    for (int j = 0; j < CC; j++) out[(size_t)node * CC + j] = acc[j] - lse;
}

// ---------------------------------------------------------------
extern "C" void kernel_launch(void* const* d_in, const int* in_sizes, int n_in,
                              void* d_out, int out_size) {
    const float* x = nullptr; const void* ei = nullptr;
    const float* W1 = nullptr; const float* b1 = nullptr;
    const float* W2 = nullptr; const float* b2 = nullptr;
    for (int i = 0; i < n_in; i++) {
        switch (in_sizes[i]) {
            case NN * FIN:   x  = (const float*)d_in[i]; break;
            case 2 * EE:     ei = d_in[i]; break;
            case FIN * HD:   W1 = (const float*)d_in[i]; break;
            case HD:         b1 = (const float*)d_in[i]; break;
            case HD * CC:    W2 = (const float*)d_in[i]; break;
            case CC:         b2 = (const float*)d_in[i]; break;
            default: break;
        }
    }
    float* out = (float*)d_out;

    detect_kernel<<<1, 32>>>((const int*)ei);
    init_deg_kernel<<<(NN + 255) / 256, 256>>>();
    build_deg_kernel<<<(EE + 255) / 256, 256>>>(ei);
    scan_bsum_kernel<<<SCAN_B, SCAN_T>>>();
    scan_boff_kernel<<<1, 32>>>();
    scan_write_kernel<<<SCAN_B, SCAN_T>>>();
    scatter_kernel<<<(ET + 255) / 256, 256>>>(ei);

    gemm1_kernel<<<NN / G1_NODES, 256>>>(x, W1, b1);

    for (int l = 0; l < 4; l++)
        agnn_kernel<<<(NN + 7) / 8, 256>>>(l & 1);

    gemm2_kernel<<<(NN + 255) / 256, 256>>>(W2, b2, out, 0);
}